// round 14
// baseline (speedup 1.0000x reference)
#include <cuda_runtime.h>
#include <math_constants.h>

#define BB 512
#define TT 1024
#define KK 48

typedef unsigned long long ull;

__device__ __forceinline__ ull pack2(float lo, float hi) {
    return ((ull)__float_as_uint(hi) << 32) | (ull)__float_as_uint(lo);
}
__device__ __forceinline__ float ulo(ull v){ return __uint_as_float((unsigned)v); }
__device__ __forceinline__ float uhi(ull v){ return __uint_as_float((unsigned)(v >> 32)); }

#define FFMA2(d,a,b,c) asm("fma.rn.f32x2 %0, %1, %2, %3;" : "=l"(d) : "l"(a), "l"(b), "l"(c))
#define FADD2(d,a,b)   asm("add.rn.f32x2 %0, %1, %2;"     : "=l"(d) : "l"(a), "l"(b))

// ---------------------------------------------------------------------------
// One block (32 threads, 1 warp) per batch. Lane l owns states 2l and 2l+1
// (lanes 24..31: zero rows, written to unread slots). LINEAR-space recurrence:
//   q_t[j] = (sum_i q_{t-1}[i] * exp(trans[j,i])) * exp(em[t,j]) * r_t
// with r_t = 1/q_{t-1}[0] at rescale steps (cadence 4; exact — q_{t-1}[0] is
// the low word of the first broadcast LDS.128 chunk, free) and r_t = 1
// otherwise; C += log(q_{t-1}[0]) at each rescale step (off-chain MUFU).
// Main loop = full 8-step groups with NO per-step branches; <=8-step tail
// carries the bound checks. Emissions: 3-stage pipeline
// (LDG group g+2 | exp of group g+1 | consume g).
// ---------------------------------------------------------------------------
__global__ void __launch_bounds__(32) crf_fused_kernel(
    const float* __restrict__ em,
    const int*   __restrict__ tags,
    const void*  __restrict__ mask,
    const float* __restrict__ trans,
    const float* __restrict__ startt,
    const float* __restrict__ endt,
    float*       __restrict__ out)
{
    const int b  = blockIdx.x;
    const int l  = threadIdx.x;            // 0..31
    const int s0 = 2 * l, s1 = 2 * l + 1;
    const bool valid = (s0 < KK);          // l < 24
    const int e0 = valid ? s0 : (KK - 2);  // clamped pair base (8B aligned)

    __shared__ __align__(16) float sh[2][64];

    // ---- sequence length (mask monotone prefix; dtype sniffed:
    //      mask[0,1] guaranteed true since lengths >= T/2) ----
    const unsigned char* mb = (const unsigned char*)mask;
    int cnt = 0;
    if (mb[1] | mb[2] | mb[3]) {
        const unsigned char* m = mb + b * TT;
        #pragma unroll
        for (int t = l; t < TT; t += 32) cnt += (m[t] != 0);
    } else {
        const unsigned int* m = (const unsigned int*)mask + b * TT;
        #pragma unroll
        for (int t = l; t < TT; t += 32) cnt += (m[t] != 0u);
    }
    #pragma unroll
    for (int o = 16; o; o >>= 1) cnt += __shfl_xor_sync(0xffffffffu, cnt, o);
    const int len = cnt;

    const size_t em_base = (size_t)b * TT * KK;

    // ---- numerator score ----
    float acc = 0.0f;
    {
        const int base = b * TT;
        for (int k = 0; k * 32 < len; k++) {
            int t = k * 32 + l;
            if (t >= 1 && t < len) {
                int cur  = tags[base + t];
                int prev = tags[base + t - 1];
                acc += em[em_base + (size_t)t * KK + cur] + trans[prev * KK + cur];
            }
        }
        #pragma unroll
        for (int o = 16; o; o >>= 1) acc += __shfl_xor_sync(0xffffffffu, acc, o);
    }

    // ---- exp(transitions) rows for both owned states (packed f32x2) ----
    ull eTa[24], eTb[24];
    #pragma unroll
    for (int i = 0; i < 24; i++) {
        eTa[i] = valid ? pack2(__expf(trans[s0 * KK + 2 * i]),
                               __expf(trans[s0 * KK + 2 * i + 1])) : 0ULL;
        eTb[i] = valid ? pack2(__expf(trans[s1 * KK + 2 * i]),
                               __expf(trans[s1 * KK + 2 * i + 1])) : 0ULL;
    }
    const float eend0 = valid ? __expf(endt[s0]) : 0.0f;
    const float eend1 = valid ? __expf(endt[s1]) : 0.0f;

    // ---- init t = 0 ----
    const float c0 = startt[0] + em[em_base + 0];   // alpha0[0], all lanes
    float q0v = valid ? __expf(startt[s0] + em[em_base + s0] - c0) : 0.0f;
    float q1v = valid ? __expf(startt[s1] + em[em_base + s1] - c0) : 0.0f;
    ((float2*)sh[0])[l] = make_float2(q0v, q1v);
    float C = c0;
    __syncthreads();

    // ---- emission pipeline: prime ----
    float2 EA[8], EB[8], R[8];
    #pragma unroll
    for (int s = 0; s < 8; s++) {               // exp for t = 1..8 (exposed once)
        int tt = 1 + s; tt = (tt < TT) ? tt : (TT - 1);
        float2 v = *(const float2*)&em[em_base + (size_t)tt * KK + e0];
        EA[s] = make_float2(__expf(v.x), __expf(v.y));
    }
    #pragma unroll
    for (int s = 0; s < 8; s++) {               // raw for t = 9..16
        int tt = 9 + s; tt = (tt < TT) ? tt : (TT - 1);
        R[s] = *(const float2*)&em[em_base + (size_t)tt * KK + e0];
    }

    // one step. APPLY: exact rescale by q_{t-1}[0] + C bookkeeping.
    // skip:  q = u * E (scale carried forward inside q, captured at next APPLY)
#define STEP(RD, WR, EE, APPLY) do {                                           \
    const double2* P2 = (const double2*)sh[RD];                                \
    double2 p0 = P2[0];                                                        \
    float Er0, Er1;                                                            \
    if (APPLY) {                                                               \
        float q0prev = ulo(__double_as_longlong(p0.x)); /* chunk0 low, free */ \
        float r = __fdividef(1.0f, q0prev);  /* ready early, used late */      \
        Er0 = (EE).x * r;                                                      \
        Er1 = (EE).y * r;                                                      \
        C += __logf(q0prev);             /* off-chain MUFU side chain */       \
    } else {                                                                   \
        Er0 = (EE).x;                                                          \
        Er1 = (EE).y;                                                          \
    }                                                                          \
    ull A0=0,A1=0,A2=0,A3=0,B0=0,B1=0,B2=0,B3=0;                               \
    {                                                                          \
        ull xa = __double_as_longlong(p0.x), xb = __double_as_longlong(p0.y);  \
        FFMA2(A0, xa, eTa[0], A0);  FFMA2(A1, xb, eTa[1], A1);                 \
        FFMA2(B0, xa, eTb[0], B0);  FFMA2(B1, xb, eTb[1], B1);                 \
    }                                                                          \
    _Pragma("unroll")                                                          \
    for (int i = 1; i < 12; i++) {                                             \
        double2 q = P2[i];                                                     \
        ull xa = __double_as_longlong(q.x), xb = __double_as_longlong(q.y);    \
        if (i & 1) {                                                           \
            FFMA2(A2, xa, eTa[2*i+0], A2);  FFMA2(A3, xb, eTa[2*i+1], A3);     \
            FFMA2(B2, xa, eTb[2*i+0], B2);  FFMA2(B3, xb, eTb[2*i+1], B3);     \
        } else {                                                               \
            FFMA2(A0, xa, eTa[2*i+0], A0);  FFMA2(A1, xb, eTa[2*i+1], A1);     \
            FFMA2(B0, xa, eTb[2*i+0], B0);  FFMA2(B1, xb, eTb[2*i+1], B1);     \
        }                                                                      \
    }                                                                          \
    FADD2(A0, A0, A1); FADD2(A2, A2, A3); FADD2(A0, A0, A2);                   \
    FADD2(B0, B0, B1); FADD2(B2, B2, B3); FADD2(B0, B0, B2);                   \
    float u0 = ulo(A0) + uhi(A0);                                              \
    float u1 = ulo(B0) + uhi(B0);                                              \
    q0v = u0 * Er0;                   /* single-FMUL tail */                   \
    q1v = u1 * Er1;                                                            \
    ((float2*)sh[WR])[l] = make_float2(q0v, q1v);                              \
    __syncthreads();                  /* nw=1 BAR, ~3 cyc */                   \
} while (0)

    // full group: ENXT = exp(R) (loads from last group, landed); R refilled
    // for the group after next; 8 UNCONDITIONAL steps (no per-step branches).
    // Rescale at s=0 and s=4 (cadence 4). t0 stays odd -> RD = s&1.
#define GROUP_FULL(ECUR, ENXT) do {                                            \
    _Pragma("unroll")                                                          \
    for (int s = 0; s < 8; s++)                                                \
        ENXT[s] = make_float2(__expf(R[s].x), __expf(R[s].y));                 \
    _Pragma("unroll")                                                          \
    for (int s = 0; s < 8; s++) {                                              \
        int tt = t0 + 16 + s; tt = (tt < TT) ? tt : (TT - 1);                  \
        R[s] = *(const float2*)&em[em_base + (size_t)tt * KK + e0];            \
    }                                                                          \
    STEP(0, 1, ECUR[0], 1);                                                    \
    STEP(1, 0, ECUR[1], 0);                                                    \
    STEP(0, 1, ECUR[2], 0);                                                    \
    STEP(1, 0, ECUR[3], 0);                                                    \
    STEP(0, 1, ECUR[4], 1);                                                    \
    STEP(1, 0, ECUR[5], 0);                                                    \
    STEP(0, 1, ECUR[6], 0);                                                    \
    STEP(1, 0, ECUR[7], 0);                                                    \
    t0 += 8;                                                                   \
} while (0)

    int t0 = 1;
    int useA = 1;
    // main loop: only FULL 8-step groups, zero per-step checks
    while (t0 + 8 <= len) {
        if (useA) GROUP_FULL(EA, EB);
        else      GROUP_FULL(EB, EA);
        useA ^= 1;
    }
    // tail: 0..7 steps from the buffer the last full group prefetched;
    // every tail step rescales (APPLY=1) — correct regardless of cadence phase
    {
        const int nrem = len - t0;
        #pragma unroll
        for (int s = 0; s < 8; s++) {
            if (s >= nrem) break;
            float2 E = useA ? EA[s] : EB[s];
            if (s & 1) STEP(1, 0, E, 1);
            else       STEP(0, 1, E, 1);
        }
    }
#undef GROUP_FULL
#undef STEP

    // ---- out = score - (C + log( sum_j q_j * exp(end_j) )) ----
    float tot = q0v * eend0 + q1v * eend1;
    #pragma unroll
    for (int o = 16; o; o >>= 1) tot += __shfl_xor_sync(0xffffffffu, tot, o);

    if (l == 0) {
        const int base = b * TT;
        int tag0 = tags[base];
        float score = startt[tag0] + em[em_base + tag0] + acc
                    + endt[tags[base + len - 1]];
        out[b] = score - (C + __logf(tot));
    }
}

extern "C" void kernel_launch(void* const* d_in, const int* in_sizes, int n_in,
                              void* d_out, int out_size)
{
    const float* em    = (const float*)d_in[0];
    const int*   tags  = (const int*)d_in[1];
    const void*  mask  = d_in[2];
    const float* trans = (const float*)d_in[3];
    const float* stt   = (const float*)d_in[4];
    const float* ent   = (const float*)d_in[5];
    float*       out   = (float*)d_out;

    crf_fused_kernel<<<BB, 32>>>(em, tags, mask, trans, stt, ent, out);
}

// round 15
// speedup vs baseline: 2.4181x; 2.4181x over previous
#include <cuda_runtime.h>
#include <math_constants.h>

#define BB 512
#define TT 1024
#define KK 48

typedef unsigned long long ull;

__device__ __forceinline__ ull pack2(float lo, float hi) {
    return ((ull)__float_as_uint(hi) << 32) | (ull)__float_as_uint(lo);
}
__device__ __forceinline__ float ulo(ull v){ return __uint_as_float((unsigned)v); }
__device__ __forceinline__ float uhi(ull v){ return __uint_as_float((unsigned)(v >> 32)); }

#define FFMA2(d,a,b,c) asm("fma.rn.f32x2 %0, %1, %2, %3;" : "=l"(d) : "l"(a), "l"(b), "l"(c))
#define FADD2(d,a,b)   asm("add.rn.f32x2 %0, %1, %2;"     : "=l"(d) : "l"(a), "l"(b))

// ---------------------------------------------------------------------------
// One block (32 threads, 1 warp) per batch. Lane l owns states 2l and 2l+1
// (lanes 24..31: zero rows). Forward recurrence in LINEAR space:
//   q_t[j] = (sum_i q_{t-1}[i] * exp(trans[j,i])) * exp(em[t,j]) / q_{t-1}[0]
//   C via xprod: xprod *= q_{t-1}[0] each step; C += log(xprod) per group.
// q_{t-1}[0] is the low word of the first LDS.128 chunk (free) -> exact
// rescale, no shfl, no per-step logf. Emissions: 3-stage pipeline
// (LDG group g+2 | exp of group g+1 | consume g).
// ---------------------------------------------------------------------------
__global__ void __launch_bounds__(32) crf_fused_kernel(
    const float* __restrict__ em,
    const int*   __restrict__ tags,
    const void*  __restrict__ mask,
    const float* __restrict__ trans,
    const float* __restrict__ startt,
    const float* __restrict__ endt,
    float*       __restrict__ out)
{
    const int b  = blockIdx.x;
    const int l  = threadIdx.x;            // 0..31
    const int s0 = 2 * l, s1 = 2 * l + 1;
    const bool valid = (s0 < KK);          // l < 24
    const int e0 = valid ? s0 : (KK - 2);  // clamped pair base (8B aligned)

    __shared__ __align__(16) float sh[2][64];

    // ---- sequence length (mask monotone prefix; dtype sniffed:
    //      mask[0,1] guaranteed true since lengths >= T/2) ----
    const unsigned char* mb = (const unsigned char*)mask;
    int cnt = 0;
    if (mb[1] | mb[2] | mb[3]) {
        const unsigned char* m = mb + b * TT;
        #pragma unroll
        for (int t = l; t < TT; t += 32) cnt += (m[t] != 0);
    } else {
        const unsigned int* m = (const unsigned int*)mask + b * TT;
        #pragma unroll
        for (int t = l; t < TT; t += 32) cnt += (m[t] != 0u);
    }
    #pragma unroll
    for (int o = 16; o; o >>= 1) cnt += __shfl_xor_sync(0xffffffffu, cnt, o);
    const int len = cnt;

    const size_t em_base = (size_t)b * TT * KK;

    // ---- numerator score ----
    float acc = 0.0f;
    {
        const int base = b * TT;
        for (int k = 0; k * 32 < len; k++) {
            int t = k * 32 + l;
            if (t >= 1 && t < len) {
                int cur  = tags[base + t];
                int prev = tags[base + t - 1];
                acc += em[em_base + (size_t)t * KK + cur] + trans[prev * KK + cur];
            }
        }
        #pragma unroll
        for (int o = 16; o; o >>= 1) acc += __shfl_xor_sync(0xffffffffu, acc, o);
    }

    // ---- exp(transitions) rows for both owned states (packed f32x2) ----
    ull eTa[24], eTb[24];
    #pragma unroll
    for (int i = 0; i < 24; i++) {
        eTa[i] = valid ? pack2(__expf(trans[s0 * KK + 2 * i]),
                               __expf(trans[s0 * KK + 2 * i + 1])) : 0ULL;
        eTb[i] = valid ? pack2(__expf(trans[s1 * KK + 2 * i]),
                               __expf(trans[s1 * KK + 2 * i + 1])) : 0ULL;
    }
    const float eend0 = valid ? __expf(endt[s0]) : 0.0f;
    const float eend1 = valid ? __expf(endt[s1]) : 0.0f;

    // ---- init t = 0 ----
    const float c0 = startt[0] + em[em_base + 0];   // alpha0[0], all lanes
    float q0v = valid ? __expf(startt[s0] + em[em_base + s0] - c0) : 0.0f;
    float q1v = valid ? __expf(startt[s1] + em[em_base + s1] - c0) : 0.0f;
    ((float2*)sh[0])[l] = make_float2(q0v, q1v);
    float C = c0, xprod = 1.0f;
    __syncthreads();

    // ---- emission pipeline: prime ----
    float2 EA[8], EB[8], R[8];
    #pragma unroll
    for (int s = 0; s < 8; s++) {               // exp for t = 1..8 (exposed once)
        int tt = 1 + s; tt = (tt < TT) ? tt : (TT - 1);
        float2 v = *(const float2*)&em[em_base + (size_t)tt * KK + e0];
        EA[s] = make_float2(__expf(v.x), __expf(v.y));
    }
    #pragma unroll
    for (int s = 0; s < 8; s++) {               // raw for t = 9..16
        int tt = 9 + s; tt = (tt < TT) ? tt : (TT - 1);
        R[s] = *(const float2*)&em[em_base + (size_t)tt * KK + e0];
    }

#define STEP(RD, WR, EE) do {                                                  \
    const double2* P2 = (const double2*)sh[RD];                                \
    double2 p0 = P2[0];                                                        \
    float q0prev = ulo(__double_as_longlong(p0.x));  /* q_{t-1}[0], free */    \
    float r = __fdividef(1.0f, q0prev);   /* ready ~50cyc, used ~150cyc */     \
    ull A0=0,A1=0,A2=0,A3=0,B0=0,B1=0,B2=0,B3=0;                               \
    {                                                                          \
        ull xa = __double_as_longlong(p0.x), xb = __double_as_longlong(p0.y);  \
        FFMA2(A0, xa, eTa[0], A0);  FFMA2(A1, xb, eTa[1], A1);                 \
        FFMA2(B0, xa, eTb[0], B0);  FFMA2(B1, xb, eTb[1], B1);                 \
    }                                                                          \
    _Pragma("unroll")                                                          \
    for (int i = 1; i < 12; i++) {                                             \
        double2 q = P2[i];                                                     \
        ull xa = __double_as_longlong(q.x), xb = __double_as_longlong(q.y);    \
        if (i & 1) {                                                           \
            FFMA2(A2, xa, eTa[2*i+0], A2);  FFMA2(A3, xb, eTa[2*i+1], A3);     \
            FFMA2(B2, xa, eTb[2*i+0], B2);  FFMA2(B3, xb, eTb[2*i+1], B3);     \
        } else {                                                               \
            FFMA2(A0, xa, eTa[2*i+0], A0);  FFMA2(A1, xb, eTa[2*i+1], A1);     \
            FFMA2(B0, xa, eTb[2*i+0], B0);  FFMA2(B1, xb, eTb[2*i+1], B1);     \
        }                                                                      \
    }                                                                          \
    FADD2(A0, A0, A1); FADD2(A2, A2, A3); FADD2(A0, A0, A2);                   \
    FADD2(B0, B0, B1); FADD2(B2, B2, B3); FADD2(B0, B0, B2);                   \
    float u0 = ulo(A0) + uhi(A0);                                              \
    float u1 = ulo(B0) + uhi(B0);                                              \
    xprod *= q0prev;                  /* FMUL side chain (log deferred) */     \
    q0v = u0 * (EE).x * r;                                                     \
    q1v = u1 * (EE).y * r;                                                     \
    ((float2*)sh[WR])[l] = make_float2(q0v, q1v);                              \
    __syncthreads();                  /* nw=1 BAR, ~3 cyc */                   \
} while (0)

    // group: ECUR consumed now; ENXT = exp(R) (loads from last group, landed);
    // R refilled for the group after next. t0 stays odd -> RD = s&1.
#define GROUP(ECUR, ENXT) do {                                                 \
    _Pragma("unroll")                                                          \
    for (int s = 0; s < 8; s++)                                                \
        ENXT[s] = make_float2(__expf(R[s].x), __expf(R[s].y));                 \
    _Pragma("unroll")                                                          \
    for (int s = 0; s < 8; s++) {                                              \
        int tt = t0 + 16 + s; tt = (tt < TT) ? tt : (TT - 1);                  \
        R[s] = *(const float2*)&em[em_base + (size_t)tt * KK + e0];            \
    }                                                                          \
    {                                                                          \
        const int tend = (t0 + 8 < len) ? (t0 + 8) : len;                      \
        _Pragma("unroll")                                                      \
        for (int s = 0; s < 8; s++) {                                          \
            if (t0 + s >= tend) break;                                         \
            if (s & 1) STEP(1, 0, ECUR[s]);                                    \
            else       STEP(0, 1, ECUR[s]);                                    \
        }                                                                      \
    }                                                                          \
    C += __logf(xprod);               /* flush: one MUFU per 8 steps */        \
    xprod = 1.0f;                                                              \
    t0 += 8;                                                                   \
} while (0)

    int t0 = 1;
    while (t0 < len) {
        GROUP(EA, EB);
        if (t0 >= len) break;
        GROUP(EB, EA);
    }
#undef GROUP
#undef STEP

    // ---- out = score - (C + log( sum_j q_j * exp(end_j) )) ----
    float tot = q0v * eend0 + q1v * eend1;
    #pragma unroll
    for (int o = 16; o; o >>= 1) tot += __shfl_xor_sync(0xffffffffu, tot, o);

    if (l == 0) {
        const int base = b * TT;
        int tag0 = tags[base];
        float score = startt[tag0] + em[em_base + tag0] + acc
                    + endt[tags[base + len - 1]];
        out[b] = score - (C + __logf(tot));
    }
}

extern "C" void kernel_launch(void* const* d_in, const int* in_sizes, int n_in,
                              void* d_out, int out_size)
{
    const float* em    = (const float*)d_in[0];
    const int*   tags  = (const int*)d_in[1];
    const void*  mask  = d_in[2];
    const float* trans = (const float*)d_in[3];
    const float* stt   = (const float*)d_in[4];
    const float* ent   = (const float*)d_in[5];
    float*       out   = (float*)d_out;

    crf_fused_kernel<<<BB, 32>>>(em, tags, mask, trans, stt, ent, out);
}

// round 16
// speedup vs baseline: 2.4849x; 1.0276x over previous
#include <cuda_runtime.h>
#include <math_constants.h>

#define BB 512
#define TT 1024
#define KK 48

typedef unsigned long long ull;

__device__ __forceinline__ ull pack2(float lo, float hi) {
    return ((ull)__float_as_uint(hi) << 32) | (ull)__float_as_uint(lo);
}
__device__ __forceinline__ float ulo(ull v){ return __uint_as_float((unsigned)v); }
__device__ __forceinline__ float uhi(ull v){ return __uint_as_float((unsigned)(v >> 32)); }

#define FFMA2(d,a,b,c) asm("fma.rn.f32x2 %0, %1, %2, %3;" : "=l"(d) : "l"(a), "l"(b), "l"(c))
#define FADD2(d,a,b)   asm("add.rn.f32x2 %0, %1, %2;"     : "=l"(d) : "l"(a), "l"(b))

// ---------------------------------------------------------------------------
// One block (32 threads, 1 warp) per batch. Lane l owns states 2l and 2l+1
// (lanes 24..31: zero rows). Forward recurrence in LINEAR space:
//   q_t[j] = (sum_i q_{t-1}[i] * exp(trans[j,i])) * exp(em[t,j]) / q_{t-1}[0]
//   C via xprod: xprod *= q_{t-1}[0] each step; C += log(xprod) per group.
// SINGLE-BUFFER, ZERO-SYNC exchange: with one converged warp and branch-free
// control flow, instructions issue in program order; the step's STS stores a
// value data-dependent on ALL 12 LDS results, so every lane's reads complete
// before any lane's write issues -> in-place smem exchange is race-free.
// q_{t-1}[0] is the low word of the first LDS.128 chunk (free) -> exact
// rescale, no shfl, no per-step logf. Emissions: 3-stage pipeline
// (LDG group g+2 | exp of group g+1 | consume g).
// ---------------------------------------------------------------------------
__global__ void __launch_bounds__(32) crf_fused_kernel(
    const float* __restrict__ em,
    const int*   __restrict__ tags,
    const void*  __restrict__ mask,
    const float* __restrict__ trans,
    const float* __restrict__ startt,
    const float* __restrict__ endt,
    float*       __restrict__ out)
{
    const int b  = blockIdx.x;
    const int l  = threadIdx.x;            // 0..31
    const int s0 = 2 * l, s1 = 2 * l + 1;
    const bool valid = (s0 < KK);          // l < 24
    const int e0 = valid ? s0 : (KK - 2);  // clamped pair base (8B aligned)

    __shared__ __align__(16) float sh[64];

    // ---- sequence length (mask monotone prefix; dtype sniffed:
    //      mask[0,1] guaranteed true since lengths >= T/2) ----
    const unsigned char* mb = (const unsigned char*)mask;
    int cnt = 0;
    if (mb[1] | mb[2] | mb[3]) {
        const unsigned char* m = mb + b * TT;
        #pragma unroll
        for (int t = l; t < TT; t += 32) cnt += (m[t] != 0);
    } else {
        const unsigned int* m = (const unsigned int*)mask + b * TT;
        #pragma unroll
        for (int t = l; t < TT; t += 32) cnt += (m[t] != 0u);
    }
    #pragma unroll
    for (int o = 16; o; o >>= 1) cnt += __shfl_xor_sync(0xffffffffu, cnt, o);
    const int len = cnt;

    const size_t em_base = (size_t)b * TT * KK;

    // ---- numerator score ----
    float acc = 0.0f;
    {
        const int base = b * TT;
        for (int k = 0; k * 32 < len; k++) {
            int t = k * 32 + l;
            if (t >= 1 && t < len) {
                int cur  = tags[base + t];
                int prev = tags[base + t - 1];
                acc += em[em_base + (size_t)t * KK + cur] + trans[prev * KK + cur];
            }
        }
        #pragma unroll
        for (int o = 16; o; o >>= 1) acc += __shfl_xor_sync(0xffffffffu, acc, o);
    }

    // ---- exp(transitions) rows for both owned states (packed f32x2) ----
    ull eTa[24], eTb[24];
    #pragma unroll
    for (int i = 0; i < 24; i++) {
        eTa[i] = valid ? pack2(__expf(trans[s0 * KK + 2 * i]),
                               __expf(trans[s0 * KK + 2 * i + 1])) : 0ULL;
        eTb[i] = valid ? pack2(__expf(trans[s1 * KK + 2 * i]),
                               __expf(trans[s1 * KK + 2 * i + 1])) : 0ULL;
    }
    const float eend0 = valid ? __expf(endt[s0]) : 0.0f;
    const float eend1 = valid ? __expf(endt[s1]) : 0.0f;

    // ---- init t = 0 ----
    const float c0 = startt[0] + em[em_base + 0];   // alpha0[0], all lanes
    float q0v = valid ? __expf(startt[s0] + em[em_base + s0] - c0) : 0.0f;
    float q1v = valid ? __expf(startt[s1] + em[em_base + s1] - c0) : 0.0f;
    ((float2*)sh)[l] = make_float2(q0v, q1v);
    float C = c0, xprod = 1.0f;

    // ---- emission pipeline: prime ----
    float2 EA[8], EB[8], R[8];
    #pragma unroll
    for (int s = 0; s < 8; s++) {               // exp for t = 1..8 (exposed once)
        int tt = 1 + s; tt = (tt < TT) ? tt : (TT - 1);
        float2 v = *(const float2*)&em[em_base + (size_t)tt * KK + e0];
        EA[s] = make_float2(__expf(v.x), __expf(v.y));
    }
    #pragma unroll
    for (int s = 0; s < 8; s++) {               // raw for t = 9..16
        int tt = 9 + s; tt = (tt < TT) ? tt : (TT - 1);
        R[s] = *(const float2*)&em[em_base + (size_t)tt * KK + e0];
    }

#define STEP(EE) do {                                                          \
    const double2* P2 = (const double2*)sh;                                    \
    double2 p0 = P2[0];                                                        \
    float q0prev = ulo(__double_as_longlong(p0.x));  /* q_{t-1}[0], free */    \
    float r = __fdividef(1.0f, q0prev);   /* ready early, used late */         \
    ull A0=0,A1=0,A2=0,A3=0,B0=0,B1=0,B2=0,B3=0;                               \
    {                                                                          \
        ull xa = __double_as_longlong(p0.x), xb = __double_as_longlong(p0.y);  \
        FFMA2(A0, xa, eTa[0], A0);  FFMA2(A1, xb, eTa[1], A1);                 \
        FFMA2(B0, xa, eTb[0], B0);  FFMA2(B1, xb, eTb[1], B1);                 \
    }                                                                          \
    _Pragma("unroll")                                                          \
    for (int i = 1; i < 12; i++) {                                             \
        double2 q = P2[i];                                                     \
        ull xa = __double_as_longlong(q.x), xb = __double_as_longlong(q.y);    \
        if (i & 1) {                                                           \
            FFMA2(A2, xa, eTa[2*i+0], A2);  FFMA2(A3, xb, eTa[2*i+1], A3);     \
            FFMA2(B2, xa, eTb[2*i+0], B2);  FFMA2(B3, xb, eTb[2*i+1], B3);     \
        } else {                                                               \
            FFMA2(A0, xa, eTa[2*i+0], A0);  FFMA2(A1, xb, eTa[2*i+1], A1);     \
            FFMA2(B0, xa, eTb[2*i+0], B0);  FFMA2(B1, xb, eTb[2*i+1], B1);     \
        }                                                                      \
    }                                                                          \
    FADD2(A0, A0, A1); FADD2(A2, A2, A3); FADD2(A0, A0, A2);                   \
    FADD2(B0, B0, B1); FADD2(B2, B2, B3); FADD2(B0, B0, B2);                   \
    float u0 = ulo(A0) + uhi(A0);                                              \
    float u1 = ulo(B0) + uhi(B0);                                              \
    xprod *= q0prev;                  /* FMUL side chain (log deferred) */     \
    q0v = u0 * (EE).x * r;                                                     \
    q1v = u1 * (EE).y * r;                                                     \
    ((float2*)sh)[l] = make_float2(q0v, q1v);  /* in-place: reads all done */  \
} while (0)

    // group: ECUR consumed now; ENXT = exp(R) (loads from last group, landed);
    // R refilled for the group after next.
#define GROUP(ECUR, ENXT) do {                                                 \
    _Pragma("unroll")                                                          \
    for (int s = 0; s < 8; s++)                                                \
        ENXT[s] = make_float2(__expf(R[s].x), __expf(R[s].y));                 \
    _Pragma("unroll")                                                          \
    for (int s = 0; s < 8; s++) {                                              \
        int tt = t0 + 16 + s; tt = (tt < TT) ? tt : (TT - 1);                  \
        R[s] = *(const float2*)&em[em_base + (size_t)tt * KK + e0];            \
    }                                                                          \
    {                                                                          \
        const int tend = (t0 + 8 < len) ? (t0 + 8) : len;                      \
        _Pragma("unroll")                                                      \
        for (int s = 0; s < 8; s++) {                                          \
            if (t0 + s >= tend) break;                                         \
            STEP(ECUR[s]);                                                     \
        }                                                                      \
    }                                                                          \
    C += __logf(xprod);               /* flush: one MUFU per 8 steps */        \
    xprod = 1.0f;                                                              \
    t0 += 8;                                                                   \
} while (0)

    int t0 = 1;
    while (t0 < len) {
        GROUP(EA, EB);
        if (t0 >= len) break;
        GROUP(EB, EA);
    }
#undef GROUP
#undef STEP

    // ---- out = score - (C + log( sum_j q_j * exp(end_j) )) ----
    float tot = q0v * eend0 + q1v * eend1;
    #pragma unroll
    for (int o = 16; o; o >>= 1) tot += __shfl_xor_sync(0xffffffffu, tot, o);

    if (l == 0) {
        const int base = b * TT;
        int tag0 = tags[base];
        float score = startt[tag0] + em[em_base + tag0] + acc
                    + endt[tags[base + len - 1]];
        out[b] = score - (C + __logf(tot));
    }
}

extern "C" void kernel_launch(void* const* d_in, const int* in_sizes, int n_in,
                              void* d_out, int out_size)
{
    const float* em    = (const float*)d_in[0];
    const int*   tags  = (const int*)d_in[1];
    const void*  mask  = d_in[2];
    const float* trans = (const float*)d_in[3];
    const float* stt   = (const float*)d_in[4];
    const float* ent   = (const float*)d_in[5];
    float*       out   = (float*)d_out;

    crf_fused_kernel<<<BB, 32>>>(em, tags, mask, trans, stt, ent, out);
}